// round 16
// baseline (speedup 1.0000x reference)
#include <cuda_runtime.h>
#include <cuda_fp16.h>
#include <cstdint>
#include <math.h>

typedef unsigned long long ull;
typedef unsigned int uint;

#define B_     32
#define T0     1600
#define C0     80
#define T1     800
#define D_     512
#define VOCABN 1000
#define HIDN   512
#define USTEPS 200
#define EPSV   1e-3f
#define TPAD   832

// ---------------- scratch (static device globals; no allocation) ----------------
__device__ float g_bn[160];
__device__ float g_hstate[2][B_ * HIDN];
__device__ float g_mhp[8][B_ * 1536];
__device__ float g_mx[USTEPS * B_ * 1536];          // precomputed onehot@gru_kernel + bi
__device__ float g_scoresall[USTEPS * B_ * T1];
__device__ float g_logitsall[USTEPS * B_ * VOCABN];
// fp16 side
__device__ __half g_sa0[B_ * T1 * D_];
__device__ __half g_sa1[B_ * T1 * D_];
__device__ __half g_wh[4 * 512 * 2560];             // tcr weights [l][n][kin]
__device__ __half g_x16[B_ * T0 * 128];             // bn-applied input, channel-padded
__device__ __half g_wc16[512 * 640];                // conv0 weights [n][5*128]
__device__ __half g_cat16[USTEPS * B_ * 1024];
__device__ __half g_alpha16[USTEPS * B_ * TPAD];
__device__ __half g_encT16[B_ * D_ * TPAD];
__device__ __half g_fcwT16[1024 * 1024];

// ---------------- packed f32x2 helpers (for gru_part) ----------------
__device__ __forceinline__ void fma2(ull& d, ull a, ull b) {
    asm("fma.rn.f32x2 %0, %1, %2, %0;" : "+l"(d) : "l"(a), "l"(b));
}
__device__ __forceinline__ ull pack2(float x) {
    ull r;
    asm("mov.b64 %0, {%1, %1};" : "=l"(r) : "f"(x));
    return r;
}
__device__ __forceinline__ float2 unpack2(ull v) {
    float2 f;
    asm("mov.b64 {%0, %1}, %2;" : "=f"(f.x), "=f"(f.y) : "l"(v));
    return f;
}

// ---------------- mma.sync / ldmatrix / cp.async helpers ----------------
__device__ __forceinline__ uint32_t smem_to_u32(const void* p) {
    uint32_t a;
    asm("{ .reg .u64 t; cvta.to.shared.u64 t, %1; cvt.u32.u64 %0, t; }" : "=r"(a) : "l"(p));
    return a;
}
__device__ __forceinline__ void mma_f16(float* d, const uint32_t* a, const uint32_t* b) {
    asm volatile(
        "mma.sync.aligned.m16n8k16.row.col.f32.f16.f16.f32 "
        "{%0,%1,%2,%3}, {%4,%5,%6,%7}, {%8,%9}, {%0,%1,%2,%3};"
        : "+f"(d[0]), "+f"(d[1]), "+f"(d[2]), "+f"(d[3])
        : "r"(a[0]), "r"(a[1]), "r"(a[2]), "r"(a[3]), "r"(b[0]), "r"(b[1]));
}
__device__ __forceinline__ void ldsm4(uint32_t* r, uint32_t addr) {
    asm volatile("ldmatrix.sync.aligned.m8n8.x4.shared.b16 {%0,%1,%2,%3}, [%4];"
                 : "=r"(r[0]), "=r"(r[1]), "=r"(r[2]), "=r"(r[3]) : "r"(addr));
}
__device__ __forceinline__ void cp16(uint32_t d, const void* s, int sz) {
    asm volatile("cp.async.cg.shared.global [%0], [%1], 16, %2;"
                 :: "r"(d), "l"(s), "r"(sz) : "memory");
}
#define CP_COMMIT() asm volatile("cp.async.commit_group;" ::: "memory")

// ---------------- BatchNorm statistics ----------------
__global__ void __launch_bounds__(256) bn_stats_kernel(const float* __restrict__ x,
                                                       const float* __restrict__ gamma,
                                                       const float* __restrict__ beta) {
    const int c = blockIdx.x;
    const int tid = threadIdx.x;
    const int N = B_ * T0;
    float s = 0.f, sq = 0.f;
    for (int i = tid; i < N; i += 256) {
        float v = x[(size_t)i * C0 + c];
        s += v; sq += v * v;
    }
    __shared__ float rs[256], rq[256];
    rs[tid] = s; rq[tid] = sq;
    __syncthreads();
    for (int o = 128; o > 0; o >>= 1) {
        if (tid < o) { rs[tid] += rs[tid + o]; rq[tid] += rq[tid + o]; }
        __syncthreads();
    }
    if (tid == 0) {
        float mean = rs[0] / (float)N;
        float var  = rq[0] / (float)N - mean * mean;
        float sc   = gamma[c] * rsqrtf(var + EPSV);
        g_bn[c]      = sc;
        g_bn[80 + c] = beta[c] - mean * sc;
    }
}

__global__ void __launch_bounds__(512) zero_h_kernel() {
    int i = blockIdx.x * blockDim.x + threadIdx.x;
    if (i < B_ * HIDN) g_hstate[0][i] = 0.f;
}

// ---------------- mx precompute: mx[u][b][:] = gk[tok] + bi ----------------
__global__ void __launch_bounds__(256) mx_kernel(const int* __restrict__ y,
                                                 const float* __restrict__ gk,
                                                 const float* __restrict__ gb) {
    const int u = blockIdx.x, b = blockIdx.y;
    const int tok = y[b * 201 + u];
    const float* gx = gk + (size_t)tok * 1536;
    float* mp = g_mx + ((size_t)u * 32 + b) * 1536;
    for (int j = threadIdx.x; j < 1536; j += 256) mp[j] = gx[j] + gb[j];
}

// ---------------- x -> bn-normalized fp16, channel-padded to 128 ----------------
__global__ void __launch_bounds__(256) x16prep_kernel(const float* __restrict__ x) {
    int i = blockIdx.x * 256 + threadIdx.x;
    if (i >= B_ * T0 * 128) return;
    int ci = i & 127;
    int row = i >> 7;
    __half v = __float2half(0.f);
    if (ci < C0) {
        float f = x[(size_t)row * C0 + ci] * g_bn[ci] + g_bn[80 + ci];
        v = __float2half_rn(f);
    }
    g_x16[i] = v;
}

// ---------------- conv0 weights -> fp16 [n][5*128] ----------------
__global__ void __launch_bounds__(256) wc0_kernel(const float* __restrict__ w) {
    int i = blockIdx.x * 256 + threadIdx.x;
    if (i >= 512 * 640) return;
    int kin = i % 640;
    int n   = i / 640;
    int tap = kin >> 7, ci = kin & 127;
    float v = (ci < C0) ? w[(size_t)(tap * C0 + ci) * 512 + n] : 0.f;
    g_wc16[i] = __float2half_rn(v);
}

// ---------------- tcr weights transpose to fp16 [l][n][kin] ----------------
__global__ void __launch_bounds__(256) wsplit_kernel(const float* __restrict__ tcr_w) {
    __shared__ float tile[32][33];
    const int l  = blockIdx.z;
    const int k0 = blockIdx.x * 32;
    const int n0 = blockIdx.y * 32;
    const int tx = threadIdx.x, ty = threadIdx.y;
#pragma unroll
    for (int j = 0; j < 32; j += 8)
        tile[ty + j][tx] = tcr_w[((size_t)l * 2560 + k0 + ty + j) * 512 + n0 + tx];
    __syncthreads();
#pragma unroll
    for (int j = 0; j < 32; j += 8) {
        float v = tile[tx][ty + j];
        size_t di = ((size_t)l * 512 + n0 + ty + j) * 2560 + k0 + tx;
        g_wh[di] = __float2half_rn(v);
    }
}

// ---------------- enc16 [b][t][d] -> encT16 [b][d][TPAD] ----------------
__global__ void __launch_bounds__(256) enct_kernel() {
    __shared__ __half tile[32][33];
    const int b  = blockIdx.z;
    const int t0 = blockIdx.x * 32;
    const int d0 = blockIdx.y * 32;
    const int tx = threadIdx.x, ty = threadIdx.y;
#pragma unroll
    for (int j = 0; j < 32; j += 8) {
        int t = t0 + ty + j;
        __half v = __float2half(0.f);
        if (t < T1) v = g_sa0[((size_t)b * T1 + t) * 512 + d0 + tx];
        tile[ty + j][tx] = v;
    }
    __syncthreads();
#pragma unroll
    for (int j = 0; j < 32; j += 8)
        g_encT16[((size_t)b * D_ + d0 + ty + j) * TPAD + t0 + tx] = tile[tx][ty + j];
}

// ---------------- fc_w -> fcwT16 [c(pad 1024)][k 1024] ----------------
__global__ void __launch_bounds__(256) fcwt_kernel(const float* __restrict__ fw) {
    __shared__ __half tile[32][33];
    const int k0 = blockIdx.x * 32;
    const int c0 = blockIdx.y * 32;
    const int tx = threadIdx.x, ty = threadIdx.y;
#pragma unroll
    for (int j = 0; j < 32; j += 8) {
        int c = c0 + tx;
        float v = (c < VOCABN) ? fw[(size_t)(k0 + ty + j) * VOCABN + c] : 0.f;
        tile[ty + j][tx] = __float2half_rn(v);
    }
    __syncthreads();
#pragma unroll
    for (int j = 0; j < 32; j += 8)
        g_fcwT16[(size_t)(c0 + ty + j) * 1024 + k0 + tx] = tile[tx][ty + j];
}

// ---------------- unified fp16 conv (im2col GEMM) with cp.async 2-stage pipeline ----------------
// All-fp16 activation chain: residual read fp16 from the SAME tensor used as GEMM input.
#define ASTR 72
#define CBUF (128 * ASTR * 2)
#define CSTAGE (2 * CBUF)
#define CDSMEM (2 * CSTAGE)
template<int TIN, int STRIDE, int PADL, int CIN_PAD, int KCHUNKS, bool RESID>
__global__ void __launch_bounds__(256, 2) conv16_kernel(const __half* __restrict__ a16,
                                                        const __half* __restrict__ wh,
                                                        const float* __restrict__ bias,
                                                        __half* __restrict__ oh) {
    extern __shared__ __align__(16) uint8_t dsm[];
    const uint32_t base = smem_to_u32(dsm);

    const int tid = threadIdx.x;
    const int wid = tid >> 5, lane = tid & 31;
    const int n0 = blockIdx.x * 128;
    const int m0 = blockIdx.y * 128;
    const int warp_m = (wid >> 1) << 5;
    const int warp_n = (wid & 1) << 6;
    const int KTOT = KCHUNKS * 64;

    float acc[2][8][4];
#pragma unroll
    for (int i = 0; i < 2; i++)
#pragma unroll
        for (int j = 0; j < 8; j++)
#pragma unroll
            for (int r = 0; r < 4; r++) acc[i][j][r] = 0.f;

    const int lq = tid & 7;
    const int lrow = tid >> 3;

    const uint32_t aoff = (warp_m + (lane & 15)) * 144 + (lane >> 4) * 16;
    const int browoff = warp_n + (lane & 7) + ((lane >> 4) & 1) * 8;
    const uint32_t boff = browoff * 144 + ((lane >> 3) & 1) * 16;

    auto issue = [&](int c, int st) {
        const int tap = c / (CIN_PAD / 64);
        const int ci0 = (c % (CIN_PAD / 64)) * 64;
        const uint32_t sb = base + st * CSTAGE;
#pragma unroll
        for (int it = 0; it < 4; it++) {
            int ml = lrow + it * 32;
            int m  = m0 + ml;
            int bb = m / T1;
            int t  = m - bb * T1;
            int tin = t * STRIDE - PADL + tap;
            bool v = (tin >= 0 && tin < TIN);
            int tinc = v ? tin : 0;
            const __half* src = a16 + ((size_t)bb * TIN + tinc) * CIN_PAD + ci0 + lq * 8;
            cp16(sb + (uint32_t)(ml * ASTR + lq * 8) * 2, src, v ? 16 : 0);
        }
#pragma unroll
        for (int it = 0; it < 4; it++) {
            int nl = lrow + it * 32;
            const __half* src = wh + (size_t)(n0 + nl) * KTOT + c * 64 + lq * 8;
            cp16(sb + CBUF + (uint32_t)(nl * ASTR + lq * 8) * 2, src, 16);
        }
        CP_COMMIT();
    };

    issue(0, 0);
    for (int c = 0; c < KCHUNKS; c++) {
        const int st = c & 1;
        if (c + 1 < KCHUNKS) {
            issue(c + 1, (c + 1) & 1);
            asm volatile("cp.async.wait_group 1;" ::: "memory");
        } else {
            asm volatile("cp.async.wait_group 0;" ::: "memory");
        }
        __syncthreads();

        const uint32_t sb = base + st * CSTAGE;
        const uint32_t aAddr = sb + aoff;
        const uint32_t bAddr = sb + CBUF + boff;
#pragma unroll
        for (int s = 0; s < 4; s++) {
            uint32_t a[2][4];
            ldsm4(a[0], aAddr + s * 32);
            ldsm4(a[1], aAddr + s * 32 + 16 * 144);
#pragma unroll
            for (int jj = 0; jj < 4; jj++) {
                uint32_t b[4];
                ldsm4(b, bAddr + s * 32 + jj * 16 * 144);
#pragma unroll
                for (int i = 0; i < 2; i++) {
                    mma_f16(acc[i][2 * jj],     a[i], b);
                    mma_f16(acc[i][2 * jj + 1], a[i], b + 2);
                }
            }
        }
        __syncthreads();
    }

    // ---- epilogue: bias + relu (+ fp16 residual), fp16 emit ----
    const int r0 = lane >> 2;
    const int cc = (lane & 3) * 2;
#pragma unroll
    for (int i = 0; i < 2; i++) {
        int mrow = m0 + warp_m + i * 16 + r0;
#pragma unroll
        for (int j = 0; j < 8; j++) {
            int col = n0 + warp_n + j * 8 + cc;
            float2 b2 = *reinterpret_cast<const float2*>(bias + col);
#pragma unroll
            for (int half = 0; half < 2; half++) {
                int m = mrow + half * 8;
                float vx = fmaxf(acc[i][j][half * 2 + 0] + b2.x, 0.f);
                float vy = fmaxf(acc[i][j][half * 2 + 1] + b2.y, 0.f);
                if (RESID) {
                    __half2 e = *reinterpret_cast<const __half2*>(a16 + ((size_t)m * 512 + col));
                    vx += __half2float(__low2half(e));
                    vy += __half2float(__high2half(e));
                }
                *reinterpret_cast<__half2*>(oh + (size_t)m * 512 + col) = __floats2half2_rn(vx, vy);
            }
        }
    }
}

// ---------------- scores16 ----------------
__global__ void __launch_bounds__(256, 2) scores16_kernel() {
    __shared__ __align__(16) __half sA[128 * ASTR];
    __shared__ __align__(16) __half sB[128 * ASTR];
    const int tid = threadIdx.x;
    const int wid = tid >> 5, lane = tid & 31;
    const int n0 = blockIdx.x * 128;
    const int m0 = blockIdx.y * 128;
    const int b  = blockIdx.z;
    const int warp_m = (wid >> 1) << 5;
    const int warp_n = (wid & 1) << 6;

    float acc[2][8][4];
#pragma unroll
    for (int i = 0; i < 2; i++)
#pragma unroll
        for (int j = 0; j < 8; j++)
#pragma unroll
            for (int r = 0; r < 4; r++) acc[i][j][r] = 0.f;

    const int lq = tid & 7;
    const int lrow = tid >> 3;
    const uint32_t aAddr = smem_to_u32(sA) + (warp_m + (lane & 15)) * 144 + (lane >> 4) * 16;
    const int browoff = warp_n + (lane & 7) + ((lane >> 4) & 1) * 8;
    const uint32_t bAddr = smem_to_u32(sB) + browoff * 144 + ((lane >> 3) & 1) * 16;

    for (int c = 0; c < 8; c++) {
#pragma unroll
        for (int it = 0; it < 4; it++) {
            int ml = lrow + it * 32;
            int u  = m0 + ml;
            uint4 va = make_uint4(0, 0, 0, 0);
            if (u < USTEPS)
                va = *reinterpret_cast<const uint4*>(
                    g_cat16 + ((size_t)u * 32 + b) * 1024 + c * 64 + lq * 8);
            *reinterpret_cast<uint4*>(&sA[ml * ASTR + lq * 8]) = va;
        }
#pragma unroll
        for (int it = 0; it < 4; it++) {
            int nl = lrow + it * 32;
            int t  = n0 + nl;
            uint4 vb = make_uint4(0, 0, 0, 0);
            if (t < T1)
                vb = *reinterpret_cast<const uint4*>(
                    g_sa0 + ((size_t)b * T1 + t) * 512 + c * 64 + lq * 8);
            *reinterpret_cast<uint4*>(&sB[nl * ASTR + lq * 8]) = vb;
        }
        __syncthreads();
#pragma unroll
        for (int s = 0; s < 4; s++) {
            uint32_t a[2][4];
            ldsm4(a[0], aAddr + s * 32);
            ldsm4(a[1], aAddr + s * 32 + 16 * 144);
#pragma unroll
            for (int jj = 0; jj < 4; jj++) {
                uint32_t bb[4];
                ldsm4(bb, bAddr + s * 32 + jj * 16 * 144);
#pragma unroll
                for (int i = 0; i < 2; i++) {
                    mma_f16(acc[i][2 * jj],     a[i], bb);
                    mma_f16(acc[i][2 * jj + 1], a[i], bb + 2);
                }
            }
        }
        __syncthreads();
    }

    const int r0 = lane >> 2;
    const int cc = (lane & 3) * 2;
#pragma unroll
    for (int i = 0; i < 2; i++) {
        int urow = m0 + warp_m + i * 16 + r0;
#pragma unroll
        for (int j = 0; j < 8; j++) {
            int col = n0 + warp_n + j * 8 + cc;
#pragma unroll
            for (int half = 0; half < 2; half++) {
                int u = urow + half * 8;
                if (u < USTEPS && col < T1) {
                    float2 v = make_float2(acc[i][j][half * 2], acc[i][j][half * 2 + 1]);
                    *reinterpret_cast<float2*>(
                        g_scoresall + ((size_t)u * 32 + b) * T1 + col) = v;
                }
            }
        }
    }
}

// ---------------- ctx16 ----------------
__global__ void __launch_bounds__(256, 2) ctx16_kernel() {
    __shared__ __align__(16) __half sA[128 * ASTR];
    __shared__ __align__(16) __half sB[128 * ASTR];
    const int tid = threadIdx.x;
    const int wid = tid >> 5, lane = tid & 31;
    const int n0 = blockIdx.x * 128;
    const int m0 = blockIdx.y * 128;
    const int b  = blockIdx.z;
    const int warp_m = (wid >> 1) << 5;
    const int warp_n = (wid & 1) << 6;

    float acc[2][8][4];
#pragma unroll
    for (int i = 0; i < 2; i++)
#pragma unroll
        for (int j = 0; j < 8; j++)
#pragma unroll
            for (int r = 0; r < 4; r++) acc[i][j][r] = 0.f;

    const int lq = tid & 7;
    const int lrow = tid >> 3;
    const uint32_t aAddr = smem_to_u32(sA) + (warp_m + (lane & 15)) * 144 + (lane >> 4) * 16;
    const int browoff = warp_n + (lane & 7) + ((lane >> 4) & 1) * 8;
    const uint32_t bAddr = smem_to_u32(sB) + browoff * 144 + ((lane >> 3) & 1) * 16;

    for (int c = 0; c < 13; c++) {
#pragma unroll
        for (int it = 0; it < 4; it++) {
            int ml = lrow + it * 32;
            int u  = m0 + ml;
            uint4 va = make_uint4(0, 0, 0, 0);
            if (u < USTEPS)
                va = *reinterpret_cast<const uint4*>(
                    g_alpha16 + ((size_t)u * 32 + b) * TPAD + c * 64 + lq * 8);
            *reinterpret_cast<uint4*>(&sA[ml * ASTR + lq * 8]) = va;
        }
#pragma unroll
        for (int it = 0; it < 4; it++) {
            int nl = lrow + it * 32;
            *reinterpret_cast<uint4*>(&sB[nl * ASTR + lq * 8]) =
                *reinterpret_cast<const uint4*>(
                    g_encT16 + ((size_t)b * D_ + n0 + nl) * TPAD + c * 64 + lq * 8);
        }
        __syncthreads();
#pragma unroll
        for (int s = 0; s < 4; s++) {
            uint32_t a[2][4];
            ldsm4(a[0], aAddr + s * 32);
            ldsm4(a[1], aAddr + s * 32 + 16 * 144);
#pragma unroll
            for (int jj = 0; jj < 4; jj++) {
                uint32_t bb[4];
                ldsm4(bb, bAddr + s * 32 + jj * 16 * 144);
#pragma unroll
                for (int i = 0; i < 2; i++) {
                    mma_f16(acc[i][2 * jj],     a[i], bb);
                    mma_f16(acc[i][2 * jj + 1], a[i], bb + 2);
                }
            }
        }
        __syncthreads();
    }

    const int r0 = lane >> 2;
    const int cc = (lane & 3) * 2;
#pragma unroll
    for (int i = 0; i < 2; i++) {
        int urow = m0 + warp_m + i * 16 + r0;
#pragma unroll
        for (int j = 0; j < 8; j++) {
            int col = n0 + warp_n + j * 8 + cc;
#pragma unroll
            for (int half = 0; half < 2; half++) {
                int u = urow + half * 8;
                if (u < USTEPS) {
                    *reinterpret_cast<__half2*>(
                        g_cat16 + ((size_t)u * 32 + b) * 1024 + 512 + col) =
                        __floats2half2_rn(acc[i][j][half * 2], acc[i][j][half * 2 + 1]);
                }
            }
        }
    }
}

// ---------------- fc16 ----------------
__global__ void __launch_bounds__(256, 2) fc16_kernel(const float* __restrict__ fb) {
    __shared__ __align__(16) __half sA[128 * ASTR];
    __shared__ __align__(16) __half sB[128 * ASTR];
    const int tid = threadIdx.x;
    const int wid = tid >> 5, lane = tid & 31;
    const int n0 = blockIdx.x * 128;
    const int m0 = blockIdx.y * 128;
    const int warp_m = (wid >> 1) << 5;
    const int warp_n = (wid & 1) << 6;

    float acc[2][8][4];
#pragma unroll
    for (int i = 0; i < 2; i++)
#pragma unroll
        for (int j = 0; j < 8; j++)
#pragma unroll
            for (int r = 0; r < 4; r++) acc[i][j][r] = 0.f;

    const int lq = tid & 7;
    const int lrow = tid >> 3;
    const uint32_t aAddr = smem_to_u32(sA) + (warp_m + (lane & 15)) * 144 + (lane >> 4) * 16;
    const int browoff = warp_n + (lane & 7) + ((lane >> 4) & 1) * 8;
    const uint32_t bAddr = smem_to_u32(sB) + browoff * 144 + ((lane >> 3) & 1) * 16;

    for (int c = 0; c < 16; c++) {
#pragma unroll
        for (int it = 0; it < 4; it++) {
            int ml = lrow + it * 32;
            *reinterpret_cast<uint4*>(&sA[ml * ASTR + lq * 8]) =
                *reinterpret_cast<const uint4*>(
                    g_cat16 + (size_t)(m0 + ml) * 1024 + c * 64 + lq * 8);
        }
#pragma unroll
        for (int it = 0; it < 4; it++) {
            int nl = lrow + it * 32;
            *reinterpret_cast<uint4*>(&sB[nl * ASTR + lq * 8]) =
                *reinterpret_cast<const uint4*>(
                    g_fcwT16 + (size_t)(n0 + nl) * 1024 + c * 64 + lq * 8);
        }
        __syncthreads();
#pragma unroll
        for (int s = 0; s < 4; s++) {
            uint32_t a[2][4];
            ldsm4(a[0], aAddr + s * 32);
            ldsm4(a[1], aAddr + s * 32 + 16 * 144);
#pragma unroll
            for (int jj = 0; jj < 4; jj++) {
                uint32_t bb[4];
                ldsm4(bb, bAddr + s * 32 + jj * 16 * 144);
#pragma unroll
                for (int i = 0; i < 2; i++) {
                    mma_f16(acc[i][2 * jj],     a[i], bb);
                    mma_f16(acc[i][2 * jj + 1], a[i], bb + 2);
                }
            }
        }
        __syncthreads();
    }

    const int r0 = lane >> 2;
    const int cc = (lane & 3) * 2;
#pragma unroll
    for (int i = 0; i < 2; i++) {
        int mrow = m0 + warp_m + i * 16 + r0;
#pragma unroll
        for (int j = 0; j < 8; j++) {
            int col = n0 + warp_n + j * 8 + cc;
            if (col < VOCABN) {
                float2 b2 = *reinterpret_cast<const float2*>(fb + col);
#pragma unroll
                for (int half = 0; half < 2; half++) {
                    int m = mrow + half * 8;
                    float2 v = make_float2(acc[i][j][half * 2] + b2.x,
                                           acc[i][j][half * 2 + 1] + b2.y);
                    *reinterpret_cast<float2*>(g_logitsall + (size_t)m * 1000 + col) = v;
                }
            }
        }
    }
}

// ---------------- Recurrence kernel A: mh partials ----------------
__global__ void __launch_bounds__(256) gru_part_kernel(const float* __restrict__ grk, int u) {
    __shared__ float Hs[16][33];
    __shared__ __align__(16) float Ws[16][128];
    const float* h = g_hstate[u & 1];
    const int tid = threadIdx.x;
    const int n0 = blockIdx.x * 128;
    const int kb = blockIdx.y * 64;
    const int nx = tid & 31;
    const int my = tid >> 5;

    ull acc[4][2];
#pragma unroll
    for (int i = 0; i < 4; i++) { acc[i][0] = 0ull; acc[i][1] = 0ull; }

    for (int k0 = 0; k0 < 64; k0 += 16) {
#pragma unroll
        for (int it = 0; it < 2; it++) {
            int e = tid + it * 256;
            int kk = e & 15, m = e >> 4;
            Hs[kk][m] = h[m * 512 + kb + k0 + kk];
        }
#pragma unroll
        for (int it = 0; it < 2; it++) {
            int s = tid + it * 256;
            int cq = s & 31, kr = s >> 5;
            *reinterpret_cast<float4*>(&Ws[kr][cq << 2]) =
                *reinterpret_cast<const float4*>(grk + (size_t)(kb + k0 + kr) * 1536 + n0 + (cq << 2));
        }
        __syncthreads();
#pragma unroll
        for (int kk = 0; kk < 16; kk++) {
            ulonglong2 bp = *reinterpret_cast<const ulonglong2*>(&Ws[kk][nx << 2]);
#pragma unroll
            for (int i = 0; i < 4; i++) {
                ull ad = pack2(Hs[kk][(my << 2) + i]);
                fma2(acc[i][0], ad, bp.x);
                fma2(acc[i][1], ad, bp.y);
            }
        }
        __syncthreads();
    }
    float* outp = g_mhp[blockIdx.y];
#pragma unroll
    for (int i = 0; i < 4; i++) {
        float2 v0 = unpack2(acc[i][0]);
        float2 v1 = unpack2(acc[i][1]);
        *reinterpret_cast<float4*>(&outp[((my << 2) + i) * 1536 + n0 + (nx << 2)]) =
            make_float4(v0.x, v0.y, v1.x, v1.y);
    }
}

// ---------------- Recurrence kernel B: sum 8 partials + GRU gates (mx precomputed) ----------------
__global__ void __launch_bounds__(512) gru_gates_kernel(const float* __restrict__ gb, int u) {
    const int b = blockIdx.x;
    const int j = threadIdx.x;
    float hz = 0.f, hr = 0.f, hh = 0.f;
#pragma unroll
    for (int c = 0; c < 8; c++) {
        const float* p = g_mhp[c] + b * 1536;
        hz += p[j];
        hr += p[512 + j];
        hh += p[1024 + j];
    }
    const float* br = gb + 1536;
    const float* mx = g_mx + ((size_t)u * 32 + b) * 1536;
    float xz = mx[j];
    float xr = mx[512 + j];
    float xh = mx[1024 + j];
    hz += br[j];
    hr += br[512 + j];
    hh += br[1024 + j];
    float z = 1.f / (1.f + expf(-(xz + hz)));
    float r = 1.f / (1.f + expf(-(xr + hr)));
    float cand = tanhf(xh + r * hh);
    float hold = g_hstate[u & 1][b * 512 + j];
    float hn = z * hold + (1.f - z) * cand;
    g_hstate[(u + 1) & 1][b * 512 + j] = hn;
    g_cat16[((size_t)u * 32 + b) * 1024 + j] = __float2half_rn(hn);
}

// ---------------- Batched softmax over 800 -> alpha16 (padded) ----------------
__global__ void __launch_bounds__(256) sm800_kernel() {
    const int row = blockIdx.x;
    const int tid = threadIdx.x;
    const float* sp = g_scoresall + (size_t)row * T1;
    __half* ap = g_alpha16 + (size_t)row * TPAD;
    __shared__ float sa[800];
    __shared__ float red[8], red2[8];
    const int w = tid >> 5, lane = tid & 31;

    float m = -1e30f;
    for (int t = tid; t < 800; t += 256) {
        float v = sp[t];
        sa[t] = v;
        m = fmaxf(m, v);
    }
#pragma unroll
    for (int o = 16; o; o >>= 1) m = fmaxf(m, __shfl_xor_sync(0xffffffffu, m, o));
    if (lane == 0) red[w] = m;
    __syncthreads();
    float mm = red[0];
#pragma unroll
    for (int i = 1; i < 8; i++) mm = fmaxf(mm, red[i]);

    float ps = 0.f;
    for (int t = tid; t < 800; t += 256) {
        float e = expf(sa[t] - mm);
        sa[t] = e;
        ps += e;
    }
#pragma unroll
    for (int o = 16; o; o >>= 1) ps += __shfl_xor_sync(0xffffffffu, ps, o);
    if (lane == 0) red2[w] = ps;
    __syncthreads();
    float sum = 0.f;
#pragma unroll
    for (int i = 0; i < 8; i++) sum += red2[i];
    const float inv = 1.f / sum;

    for (int t = tid; t < 800; t += 256) ap[t] = __float2half_rn(sa[t] * inv);
    if (tid < 32) ap[800 + tid] = __float2half(0.f);
}

// ---------------- Batched output softmax ----------------
__global__ void __launch_bounds__(256) outsm_all_kernel(float* __restrict__ out) {
    const int m = blockIdx.x;
    const int u = m >> 5, b = m & 31;
    const int tid = threadIdx.x;
    __shared__ float sh[1000];
    __shared__ float red[8], red2[8];
    const int w = tid >> 5, lane = tid & 31;
    const float* lp = g_logitsall + (size_t)m * 1000;

    float mx = -1e30f;
    for (int c = tid; c < 1000; c += 256) {
        float v = lp[c];
        sh[c] = v;
        mx = fmaxf(mx, v);
    }
#pragma unroll
    for (int o = 16; o; o >>= 1) mx = fmaxf(mx, __shfl_xor_sync(0xffffffffu, mx, o));
    if (lane == 0) red[w] = mx;
    __syncthreads();
    float mm = red[0];
#pragma unroll
    for (int i = 1; i < 8; i++) mm = fmaxf(mm, red[i]);

    float ps = 0.f;
    for (int c = tid; c < 1000; c += 256) {
        float e = expf(sh[c] - mm);
        sh[c] = e;
        ps += e;
    }
#pragma unroll
    for (int o = 16; o; o >>= 1) ps += __shfl_xor_sync(0xffffffffu, ps, o);
    if (lane == 0) red2[w] = ps;
    __syncthreads();
    float sum = 0.f;
#pragma unroll
    for (int i = 0; i < 8; i++) sum += red2[i];
    const float inv = 1.f / sum;

    float* op = out + ((size_t)b * USTEPS + u) * VOCABN;
    for (int c = tid; c < 1000; c += 256) op[c] = sh[c] * inv;
}

// ---------------- launch ----------------
extern "C" void kernel_launch(void* const* d_in, const int* in_sizes, int n_in,
                              void* d_out, int out_size) {
    const float* x        = (const float*)d_in[0];
    const int*   y        = (const int*)  d_in[1];
    const float* bn_gamma = (const float*)d_in[2];
    const float* bn_beta  = (const float*)d_in[3];
    const float* conv0_w  = (const float*)d_in[4];
    const float* conv0_b  = (const float*)d_in[5];
    const float* tcr_w    = (const float*)d_in[6];
    const float* tcr_b    = (const float*)d_in[7];
    const float* gru_k    = (const float*)d_in[8];
    const float* gru_rk   = (const float*)d_in[9];
    const float* gru_b    = (const float*)d_in[10];
    const float* fc_w     = (const float*)d_in[11];
    const float* fc_b     = (const float*)d_in[12];
    float* out = (float*)d_out;

    __half *a0, *a1, *wh, *x16, *wc16;
    cudaGetSymbolAddress((void**)&a0, g_sa0);
    cudaGetSymbolAddress((void**)&a1, g_sa1);
    cudaGetSymbolAddress((void**)&wh, g_wh);
    cudaGetSymbolAddress((void**)&x16, g_x16);
    cudaGetSymbolAddress((void**)&wc16, g_wc16);

    auto conv0k = conv16_kernel<T0, 2, 1, 128, 10, false>;
    auto tcrk   = conv16_kernel<T1, 1, 2, 512, 40, true>;
    cudaFuncSetAttribute(conv0k, cudaFuncAttributeMaxDynamicSharedMemorySize, CDSMEM);
    cudaFuncSetAttribute(tcrk,   cudaFuncAttributeMaxDynamicSharedMemorySize, CDSMEM);

    // ---- encoder ----
    bn_stats_kernel<<<80, 256>>>(x, bn_gamma, bn_beta);
    zero_h_kernel<<<32, 512>>>();
    dim3 wgrid(80, 16, 4);
    wsplit_kernel<<<wgrid, dim3(32, 8)>>>(tcr_w);
    fcwt_kernel<<<dim3(32, 32), dim3(32, 8)>>>(fc_w);
    wc0_kernel<<<(512 * 640 + 255) / 256, 256>>>(conv0_w);
    x16prep_kernel<<<(B_ * T0 * 128 + 255) / 256, 256>>>(x);
    mx_kernel<<<dim3(USTEPS, B_), 256>>>(y, gru_k, gru_b);

    dim3 cgrid(4, 200);
    conv0k<<<cgrid, 256, CDSMEM>>>(x16, wc16, conv0_b, a0);

    const size_t WT = (size_t)512 * 2560;
    tcrk<<<cgrid, 256, CDSMEM>>>(a0, wh + 0 * WT, tcr_b + 0 * 512, a1);
    tcrk<<<cgrid, 256, CDSMEM>>>(a1, wh + 1 * WT, tcr_b + 1 * 512, a0);
    tcrk<<<cgrid, 256, CDSMEM>>>(a0, wh + 2 * WT, tcr_b + 2 * 512, a1);
    tcrk<<<cgrid, 256, CDSMEM>>>(a1, wh + 3 * WT, tcr_b + 3 * 512, a0);
    // enc16 lives in g_sa0

    enct_kernel<<<dim3(26, 16, 32), dim3(32, 8)>>>();

    // ---- GRU recurrence ----
    dim3 pgrid(12, 8);
    for (int u = 0; u < USTEPS; u++) {
        gru_part_kernel<<<pgrid, 256>>>(gru_rk, u);
        gru_gates_kernel<<<32, 512>>>(gru_b, u);
    }

    // ---- batched tail (all fp16 mma) ----
    scores16_kernel<<<dim3(7, 2, 32), 256>>>();
    sm800_kernel<<<USTEPS * B_, 256>>>();
    ctx16_kernel<<<dim3(4, 2, 32), 256>>>();
    fc16_kernel<<<dim3(8, 50), 256>>>(fc_b);
    outsm_all_kernel<<<USTEPS * B_, 256>>>(out);
}

// round 17
// speedup vs baseline: 1.0775x; 1.0775x over previous
#include <cuda_runtime.h>
#include <cuda_fp16.h>
#include <cstdint>
#include <math.h>

typedef unsigned long long ull;
typedef unsigned int uint;

#define B_     32
#define T0     1600
#define C0     80
#define T1     800
#define D_     512
#define VOCABN 1000
#define HIDN   512
#define USTEPS 200
#define EPSV   1e-3f
#define TPAD   832

// ---------------- scratch (static device globals; no allocation) ----------------
__device__ float g_bn[160];
__device__ float g_hstate[2][B_ * HIDN];
__device__ float g_mhp[8][B_ * 1536];
__device__ float g_mx[USTEPS * B_ * 1536];          // precomputed onehot@gru_kernel + bi
__device__ float g_scoresall[USTEPS * B_ * T1];
__device__ float g_logitsall[USTEPS * B_ * VOCABN];
// fp16 side
__device__ __half g_sa0[B_ * T1 * D_];
__device__ __half g_sa1[B_ * T1 * D_];
__device__ __half g_wh[4 * 512 * 2560];             // tcr weights [l][n][kin]
__device__ __half g_x16[B_ * T0 * 128];             // bn-applied input, channel-padded
__device__ __half g_wc16[512 * 640];                // conv0 weights [n][5*128]
__device__ __half g_cat16[USTEPS * B_ * 1024];
__device__ __half g_alpha16[USTEPS * B_ * TPAD];
__device__ __half g_encT16[B_ * D_ * TPAD];
__device__ __half g_fcwT16[1024 * 1024];

// ---------------- packed f32x2 helpers (for gru_part) ----------------
__device__ __forceinline__ void fma2(ull& d, ull a, ull b) {
    asm("fma.rn.f32x2 %0, %1, %2, %0;" : "+l"(d) : "l"(a), "l"(b));
}
__device__ __forceinline__ ull pack2(float x) {
    ull r;
    asm("mov.b64 %0, {%1, %1};" : "=l"(r) : "f"(x));
    return r;
}
__device__ __forceinline__ float2 unpack2(ull v) {
    float2 f;
    asm("mov.b64 {%0, %1}, %2;" : "=f"(f.x), "=f"(f.y) : "l"(v));
    return f;
}

// ---------------- mma.sync / ldmatrix / cp.async helpers ----------------
__device__ __forceinline__ uint32_t smem_to_u32(const void* p) {
    uint32_t a;
    asm("{ .reg .u64 t; cvta.to.shared.u64 t, %1; cvt.u32.u64 %0, t; }" : "=r"(a) : "l"(p));
    return a;
}
__device__ __forceinline__ void mma_f16(float* d, const uint32_t* a, const uint32_t* b) {
    asm volatile(
        "mma.sync.aligned.m16n8k16.row.col.f32.f16.f16.f32 "
        "{%0,%1,%2,%3}, {%4,%5,%6,%7}, {%8,%9}, {%0,%1,%2,%3};"
        : "+f"(d[0]), "+f"(d[1]), "+f"(d[2]), "+f"(d[3])
        : "r"(a[0]), "r"(a[1]), "r"(a[2]), "r"(a[3]), "r"(b[0]), "r"(b[1]));
}
__device__ __forceinline__ void ldsm4(uint32_t* r, uint32_t addr) {
    asm volatile("ldmatrix.sync.aligned.m8n8.x4.shared.b16 {%0,%1,%2,%3}, [%4];"
                 : "=r"(r[0]), "=r"(r[1]), "=r"(r[2]), "=r"(r[3]) : "r"(addr));
}
__device__ __forceinline__ void cp16(uint32_t d, const void* s, int sz) {
    asm volatile("cp.async.cg.shared.global [%0], [%1], 16, %2;"
                 :: "r"(d), "l"(s), "r"(sz) : "memory");
}
#define CP_COMMIT() asm volatile("cp.async.commit_group;" ::: "memory")

// ---------------- BatchNorm statistics ----------------
__global__ void __launch_bounds__(256) bn_stats_kernel(const float* __restrict__ x,
                                                       const float* __restrict__ gamma,
                                                       const float* __restrict__ beta) {
    const int c = blockIdx.x;
    const int tid = threadIdx.x;
    const int N = B_ * T0;
    float s = 0.f, sq = 0.f;
    for (int i = tid; i < N; i += 256) {
        float v = x[(size_t)i * C0 + c];
        s += v; sq += v * v;
    }
    __shared__ float rs[256], rq[256];
    rs[tid] = s; rq[tid] = sq;
    __syncthreads();
    for (int o = 128; o > 0; o >>= 1) {
        if (tid < o) { rs[tid] += rs[tid + o]; rq[tid] += rq[tid + o]; }
        __syncthreads();
    }
    if (tid == 0) {
        float mean = rs[0] / (float)N;
        float var  = rq[0] / (float)N - mean * mean;
        float sc   = gamma[c] * rsqrtf(var + EPSV);
        g_bn[c]      = sc;
        g_bn[80 + c] = beta[c] - mean * sc;
    }
}

__global__ void __launch_bounds__(512) zero_h_kernel() {
    int i = blockIdx.x * blockDim.x + threadIdx.x;
    if (i < B_ * HIDN) g_hstate[0][i] = 0.f;
}

// ---------------- mx precompute: mx[u][b][:] = gk[tok] + bi ----------------
__global__ void __launch_bounds__(256) mx_kernel(const int* __restrict__ y,
                                                 const float* __restrict__ gk,
                                                 const float* __restrict__ gb) {
    const int u = blockIdx.x, b = blockIdx.y;
    const int tok = y[b * 201 + u];
    const float* gx = gk + (size_t)tok * 1536;
    float* mp = g_mx + ((size_t)u * 32 + b) * 1536;
    for (int j = threadIdx.x; j < 1536; j += 256) mp[j] = gx[j] + gb[j];
}

// ---------------- x -> bn-normalized fp16, channel-padded to 128 ----------------
__global__ void __launch_bounds__(256) x16prep_kernel(const float* __restrict__ x) {
    int i = blockIdx.x * 256 + threadIdx.x;
    if (i >= B_ * T0 * 128) return;
    int ci = i & 127;
    int row = i >> 7;
    __half v = __float2half(0.f);
    if (ci < C0) {
        float f = x[(size_t)row * C0 + ci] * g_bn[ci] + g_bn[80 + ci];
        v = __float2half_rn(f);
    }
    g_x16[i] = v;
}

// ---------------- conv0 weights -> fp16 [n][5*128] ----------------
__global__ void __launch_bounds__(256) wc0_kernel(const float* __restrict__ w) {
    int i = blockIdx.x * 256 + threadIdx.x;
    if (i >= 512 * 640) return;
    int kin = i % 640;
    int n   = i / 640;
    int tap = kin >> 7, ci = kin & 127;
    float v = (ci < C0) ? w[(size_t)(tap * C0 + ci) * 512 + n] : 0.f;
    g_wc16[i] = __float2half_rn(v);
}

// ---------------- tcr weights transpose to fp16 [l][n][kin] ----------------
__global__ void __launch_bounds__(256) wsplit_kernel(const float* __restrict__ tcr_w) {
    __shared__ float tile[32][33];
    const int l  = blockIdx.z;
    const int k0 = blockIdx.x * 32;
    const int n0 = blockIdx.y * 32;
    const int tx = threadIdx.x, ty = threadIdx.y;
#pragma unroll
    for (int j = 0; j < 32; j += 8)
        tile[ty + j][tx] = tcr_w[((size_t)l * 2560 + k0 + ty + j) * 512 + n0 + tx];
    __syncthreads();
#pragma unroll
    for (int j = 0; j < 32; j += 8) {
        float v = tile[tx][ty + j];
        size_t di = ((size_t)l * 512 + n0 + ty + j) * 2560 + k0 + tx;
        g_wh[di] = __float2half_rn(v);
    }
}

// ---------------- enc16 [b][t][d] -> encT16 [b][d][TPAD] ----------------
__global__ void __launch_bounds__(256) enct_kernel() {
    __shared__ __half tile[32][33];
    const int b  = blockIdx.z;
    const int t0 = blockIdx.x * 32;
    const int d0 = blockIdx.y * 32;
    const int tx = threadIdx.x, ty = threadIdx.y;
#pragma unroll
    for (int j = 0; j < 32; j += 8) {
        int t = t0 + ty + j;
        __half v = __float2half(0.f);
        if (t < T1) v = g_sa0[((size_t)b * T1 + t) * 512 + d0 + tx];
        tile[ty + j][tx] = v;
    }
    __syncthreads();
#pragma unroll
    for (int j = 0; j < 32; j += 8)
        g_encT16[((size_t)b * D_ + d0 + ty + j) * TPAD + t0 + tx] = tile[tx][ty + j];
}

// ---------------- fc_w -> fcwT16 [c(pad 1024)][k 1024] ----------------
__global__ void __launch_bounds__(256) fcwt_kernel(const float* __restrict__ fw) {
    __shared__ __half tile[32][33];
    const int k0 = blockIdx.x * 32;
    const int c0 = blockIdx.y * 32;
    const int tx = threadIdx.x, ty = threadIdx.y;
#pragma unroll
    for (int j = 0; j < 32; j += 8) {
        int c = c0 + tx;
        float v = (c < VOCABN) ? fw[(size_t)(k0 + ty + j) * VOCABN + c] : 0.f;
        tile[ty + j][tx] = __float2half_rn(v);
    }
    __syncthreads();
#pragma unroll
    for (int j = 0; j < 32; j += 8)
        g_fcwT16[(size_t)(c0 + ty + j) * 1024 + k0 + tx] = tile[tx][ty + j];
}

// ---------------- unified fp16 conv (im2col GEMM) with cp.async 2-stage pipeline ----------------
#define ASTR 72
#define CBUF (128 * ASTR * 2)
#define CSTAGE (2 * CBUF)
#define CDSMEM (2 * CSTAGE)
template<int TIN, int STRIDE, int PADL, int CIN_PAD, int KCHUNKS, bool RESID>
__global__ void __launch_bounds__(256, 2) conv16_kernel(const __half* __restrict__ a16,
                                                        const __half* __restrict__ wh,
                                                        const float* __restrict__ bias,
                                                        __half* __restrict__ oh) {
    extern __shared__ __align__(16) uint8_t dsm[];
    const uint32_t base = smem_to_u32(dsm);

    const int tid = threadIdx.x;
    const int wid = tid >> 5, lane = tid & 31;
    const int n0 = blockIdx.x * 128;
    const int m0 = blockIdx.y * 128;
    const int warp_m = (wid >> 1) << 5;
    const int warp_n = (wid & 1) << 6;
    const int KTOT = KCHUNKS * 64;

    float acc[2][8][4];
#pragma unroll
    for (int i = 0; i < 2; i++)
#pragma unroll
        for (int j = 0; j < 8; j++)
#pragma unroll
            for (int r = 0; r < 4; r++) acc[i][j][r] = 0.f;

    const int lq = tid & 7;
    const int lrow = tid >> 3;

    const uint32_t aoff = (warp_m + (lane & 15)) * 144 + (lane >> 4) * 16;
    const int browoff = warp_n + (lane & 7) + ((lane >> 4) & 1) * 8;
    const uint32_t boff = browoff * 144 + ((lane >> 3) & 1) * 16;

    auto issue = [&](int c, int st) {
        const int tap = c / (CIN_PAD / 64);
        const int ci0 = (c % (CIN_PAD / 64)) * 64;
        const uint32_t sb = base + st * CSTAGE;
#pragma unroll
        for (int it = 0; it < 4; it++) {
            int ml = lrow + it * 32;
            int m  = m0 + ml;
            int bb = m / T1;
            int t  = m - bb * T1;
            int tin = t * STRIDE - PADL + tap;
            bool v = (tin >= 0 && tin < TIN);
            int tinc = v ? tin : 0;
            const __half* src = a16 + ((size_t)bb * TIN + tinc) * CIN_PAD + ci0 + lq * 8;
            cp16(sb + (uint32_t)(ml * ASTR + lq * 8) * 2, src, v ? 16 : 0);
        }
#pragma unroll
        for (int it = 0; it < 4; it++) {
            int nl = lrow + it * 32;
            const __half* src = wh + (size_t)(n0 + nl) * KTOT + c * 64 + lq * 8;
            cp16(sb + CBUF + (uint32_t)(nl * ASTR + lq * 8) * 2, src, 16);
        }
        CP_COMMIT();
    };

    issue(0, 0);
    for (int c = 0; c < KCHUNKS; c++) {
        const int st = c & 1;
        if (c + 1 < KCHUNKS) {
            issue(c + 1, (c + 1) & 1);
            asm volatile("cp.async.wait_group 1;" ::: "memory");
        } else {
            asm volatile("cp.async.wait_group 0;" ::: "memory");
        }
        __syncthreads();

        const uint32_t sb = base + st * CSTAGE;
        const uint32_t aAddr = sb + aoff;
        const uint32_t bAddr = sb + CBUF + boff;
#pragma unroll
        for (int s = 0; s < 4; s++) {
            uint32_t a[2][4];
            ldsm4(a[0], aAddr + s * 32);
            ldsm4(a[1], aAddr + s * 32 + 16 * 144);
#pragma unroll
            for (int jj = 0; jj < 4; jj++) {
                uint32_t b[4];
                ldsm4(b, bAddr + s * 32 + jj * 16 * 144);
#pragma unroll
                for (int i = 0; i < 2; i++) {
                    mma_f16(acc[i][2 * jj],     a[i], b);
                    mma_f16(acc[i][2 * jj + 1], a[i], b + 2);
                }
            }
        }
        __syncthreads();
    }

    const int r0 = lane >> 2;
    const int cc = (lane & 3) * 2;
#pragma unroll
    for (int i = 0; i < 2; i++) {
        int mrow = m0 + warp_m + i * 16 + r0;
#pragma unroll
        for (int j = 0; j < 8; j++) {
            int col = n0 + warp_n + j * 8 + cc;
            float2 b2 = *reinterpret_cast<const float2*>(bias + col);
#pragma unroll
            for (int half = 0; half < 2; half++) {
                int m = mrow + half * 8;
                float vx = fmaxf(acc[i][j][half * 2 + 0] + b2.x, 0.f);
                float vy = fmaxf(acc[i][j][half * 2 + 1] + b2.y, 0.f);
                if (RESID) {
                    __half2 e = *reinterpret_cast<const __half2*>(a16 + ((size_t)m * 512 + col));
                    vx += __half2float(__low2half(e));
                    vy += __half2float(__high2half(e));
                }
                *reinterpret_cast<__half2*>(oh + (size_t)m * 512 + col) = __floats2half2_rn(vx, vy);
            }
        }
    }
}

// ---------------- scores16 ----------------
__global__ void __launch_bounds__(256, 2) scores16_kernel() {
    __shared__ __align__(16) __half sA[128 * ASTR];
    __shared__ __align__(16) __half sB[128 * ASTR];
    const int tid = threadIdx.x;
    const int wid = tid >> 5, lane = tid & 31;
    const int n0 = blockIdx.x * 128;
    const int m0 = blockIdx.y * 128;
    const int b  = blockIdx.z;
    const int warp_m = (wid >> 1) << 5;
    const int warp_n = (wid & 1) << 6;

    float acc[2][8][4];
#pragma unroll
    for (int i = 0; i < 2; i++)
#pragma unroll
        for (int j = 0; j < 8; j++)
#pragma unroll
            for (int r = 0; r < 4; r++) acc[i][j][r] = 0.f;

    const int lq = tid & 7;
    const int lrow = tid >> 3;
    const uint32_t aAddr = smem_to_u32(sA) + (warp_m + (lane & 15)) * 144 + (lane >> 4) * 16;
    const int browoff = warp_n + (lane & 7) + ((lane >> 4) & 1) * 8;
    const uint32_t bAddr = smem_to_u32(sB) + browoff * 144 + ((lane >> 3) & 1) * 16;

    for (int c = 0; c < 8; c++) {
#pragma unroll
        for (int it = 0; it < 4; it++) {
            int ml = lrow + it * 32;
            int u  = m0 + ml;
            uint4 va = make_uint4(0, 0, 0, 0);
            if (u < USTEPS)
                va = *reinterpret_cast<const uint4*>(
                    g_cat16 + ((size_t)u * 32 + b) * 1024 + c * 64 + lq * 8);
            *reinterpret_cast<uint4*>(&sA[ml * ASTR + lq * 8]) = va;
        }
#pragma unroll
        for (int it = 0; it < 4; it++) {
            int nl = lrow + it * 32;
            int t  = n0 + nl;
            uint4 vb = make_uint4(0, 0, 0, 0);
            if (t < T1)
                vb = *reinterpret_cast<const uint4*>(
                    g_sa0 + ((size_t)b * T1 + t) * 512 + c * 64 + lq * 8);
            *reinterpret_cast<uint4*>(&sB[nl * ASTR + lq * 8]) = vb;
        }
        __syncthreads();
#pragma unroll
        for (int s = 0; s < 4; s++) {
            uint32_t a[2][4];
            ldsm4(a[0], aAddr + s * 32);
            ldsm4(a[1], aAddr + s * 32 + 16 * 144);
#pragma unroll
            for (int jj = 0; jj < 4; jj++) {
                uint32_t bb[4];
                ldsm4(bb, bAddr + s * 32 + jj * 16 * 144);
#pragma unroll
                for (int i = 0; i < 2; i++) {
                    mma_f16(acc[i][2 * jj],     a[i], bb);
                    mma_f16(acc[i][2 * jj + 1], a[i], bb + 2);
                }
            }
        }
        __syncthreads();
    }

    const int r0 = lane >> 2;
    const int cc = (lane & 3) * 2;
#pragma unroll
    for (int i = 0; i < 2; i++) {
        int urow = m0 + warp_m + i * 16 + r0;
#pragma unroll
        for (int j = 0; j < 8; j++) {
            int col = n0 + warp_n + j * 8 + cc;
#pragma unroll
            for (int half = 0; half < 2; half++) {
                int u = urow + half * 8;
                if (u < USTEPS && col < T1) {
                    float2 v = make_float2(acc[i][j][half * 2], acc[i][j][half * 2 + 1]);
                    *reinterpret_cast<float2*>(
                        g_scoresall + ((size_t)u * 32 + b) * T1 + col) = v;
                }
            }
        }
    }
}

// ---------------- ctx16 ----------------
__global__ void __launch_bounds__(256, 2) ctx16_kernel() {
    __shared__ __align__(16) __half sA[128 * ASTR];
    __shared__ __align__(16) __half sB[128 * ASTR];
    const int tid = threadIdx.x;
    const int wid = tid >> 5, lane = tid & 31;
    const int n0 = blockIdx.x * 128;
    const int m0 = blockIdx.y * 128;
    const int b  = blockIdx.z;
    const int warp_m = (wid >> 1) << 5;
    const int warp_n = (wid & 1) << 6;

    float acc[2][8][4];
#pragma unroll
    for (int i = 0; i < 2; i++)
#pragma unroll
        for (int j = 0; j < 8; j++)
#pragma unroll
            for (int r = 0; r < 4; r++) acc[i][j][r] = 0.f;

    const int lq = tid & 7;
    const int lrow = tid >> 3;
    const uint32_t aAddr = smem_to_u32(sA) + (warp_m + (lane & 15)) * 144 + (lane >> 4) * 16;
    const int browoff = warp_n + (lane & 7) + ((lane >> 4) & 1) * 8;
    const uint32_t bAddr = smem_to_u32(sB) + browoff * 144 + ((lane >> 3) & 1) * 16;

    for (int c = 0; c < 13; c++) {
#pragma unroll
        for (int it = 0; it < 4; it++) {
            int ml = lrow + it * 32;
            int u  = m0 + ml;
            uint4 va = make_uint4(0, 0, 0, 0);
            if (u < USTEPS)
                va = *reinterpret_cast<const uint4*>(
                    g_alpha16 + ((size_t)u * 32 + b) * TPAD + c * 64 + lq * 8);
            *reinterpret_cast<uint4*>(&sA[ml * ASTR + lq * 8]) = va;
        }
#pragma unroll
        for (int it = 0; it < 4; it++) {
            int nl = lrow + it * 32;
            *reinterpret_cast<uint4*>(&sB[nl * ASTR + lq * 8]) =
                *reinterpret_cast<const uint4*>(
                    g_encT16 + ((size_t)b * D_ + n0 + nl) * TPAD + c * 64 + lq * 8);
        }
        __syncthreads();
#pragma unroll
        for (int s = 0; s < 4; s++) {
            uint32_t a[2][4];
            ldsm4(a[0], aAddr + s * 32);
            ldsm4(a[1], aAddr + s * 32 + 16 * 144);
#pragma unroll
            for (int jj = 0; jj < 4; jj++) {
                uint32_t bb[4];
                ldsm4(bb, bAddr + s * 32 + jj * 16 * 144);
#pragma unroll
                for (int i = 0; i < 2; i++) {
                    mma_f16(acc[i][2 * jj],     a[i], bb);
                    mma_f16(acc[i][2 * jj + 1], a[i], bb + 2);
                }
            }
        }
        __syncthreads();
    }

    const int r0 = lane >> 2;
    const int cc = (lane & 3) * 2;
#pragma unroll
    for (int i = 0; i < 2; i++) {
        int urow = m0 + warp_m + i * 16 + r0;
#pragma unroll
        for (int j = 0; j < 8; j++) {
            int col = n0 + warp_n + j * 8 + cc;
#pragma unroll
            for (int half = 0; half < 2; half++) {
                int u = urow + half * 8;
                if (u < USTEPS) {
                    *reinterpret_cast<__half2*>(
                        g_cat16 + ((size_t)u * 32 + b) * 1024 + 512 + col) =
                        __floats2half2_rn(acc[i][j][half * 2], acc[i][j][half * 2 + 1]);
                }
            }
        }
    }
}

// ---------------- fc16 ----------------
__global__ void __launch_bounds__(256, 2) fc16_kernel(const float* __restrict__ fb) {
    __shared__ __align__(16) __half sA[128 * ASTR];
    __shared__ __align__(16) __half sB[128 * ASTR];
    const int tid = threadIdx.x;
    const int wid = tid >> 5, lane = tid & 31;
    const int n0 = blockIdx.x * 128;
    const int m0 = blockIdx.y * 128;
    const int warp_m = (wid >> 1) << 5;
    const int warp_n = (wid & 1) << 6;

    float acc[2][8][4];
#pragma unroll
    for (int i = 0; i < 2; i++)
#pragma unroll
        for (int j = 0; j < 8; j++)
#pragma unroll
            for (int r = 0; r < 4; r++) acc[i][j][r] = 0.f;

    const int lq = tid & 7;
    const int lrow = tid >> 3;
    const uint32_t aAddr = smem_to_u32(sA) + (warp_m + (lane & 15)) * 144 + (lane >> 4) * 16;
    const int browoff = warp_n + (lane & 7) + ((lane >> 4) & 1) * 8;
    const uint32_t bAddr = smem_to_u32(sB) + browoff * 144 + ((lane >> 3) & 1) * 16;

    for (int c = 0; c < 16; c++) {
#pragma unroll
        for (int it = 0; it < 4; it++) {
            int ml = lrow + it * 32;
            *reinterpret_cast<uint4*>(&sA[ml * ASTR + lq * 8]) =
                *reinterpret_cast<const uint4*>(
                    g_cat16 + (size_t)(m0 + ml) * 1024 + c * 64 + lq * 8);
        }
#pragma unroll
        for (int it = 0; it < 4; it++) {
            int nl = lrow + it * 32;
            *reinterpret_cast<uint4*>(&sB[nl * ASTR + lq * 8]) =
                *reinterpret_cast<const uint4*>(
                    g_fcwT16 + (size_t)(n0 + nl) * 1024 + c * 64 + lq * 8);
        }
        __syncthreads();
#pragma unroll
        for (int s = 0; s < 4; s++) {
            uint32_t a[2][4];
            ldsm4(a[0], aAddr + s * 32);
            ldsm4(a[1], aAddr + s * 32 + 16 * 144);
#pragma unroll
            for (int jj = 0; jj < 4; jj++) {
                uint32_t bb[4];
                ldsm4(bb, bAddr + s * 32 + jj * 16 * 144);
#pragma unroll
                for (int i = 0; i < 2; i++) {
                    mma_f16(acc[i][2 * jj],     a[i], bb);
                    mma_f16(acc[i][2 * jj + 1], a[i], bb + 2);
                }
            }
        }
        __syncthreads();
    }

    const int r0 = lane >> 2;
    const int cc = (lane & 3) * 2;
#pragma unroll
    for (int i = 0; i < 2; i++) {
        int mrow = m0 + warp_m + i * 16 + r0;
#pragma unroll
        for (int j = 0; j < 8; j++) {
            int col = n0 + warp_n + j * 8 + cc;
            if (col < VOCABN) {
                float2 b2 = *reinterpret_cast<const float2*>(fb + col);
#pragma unroll
                for (int half = 0; half < 2; half++) {
                    int m = mrow + half * 8;
                    float2 v = make_float2(acc[i][j][half * 2] + b2.x,
                                           acc[i][j][half * 2 + 1] + b2.y);
                    *reinterpret_cast<float2*>(g_logitsall + (size_t)m * 1000 + col) = v;
                }
            }
        }
    }
}

// ---------------- Recurrence kernel A: mh partials ----------------
__global__ void __launch_bounds__(256) gru_part_kernel(const float* __restrict__ grk, int u) {
    __shared__ float Hs[16][33];
    __shared__ __align__(16) float Ws[16][128];
    const float* h = g_hstate[u & 1];
    const int tid = threadIdx.x;
    const int n0 = blockIdx.x * 128;
    const int kb = blockIdx.y * 64;
    const int nx = tid & 31;
    const int my = tid >> 5;

    ull acc[4][2];
#pragma unroll
    for (int i = 0; i < 4; i++) { acc[i][0] = 0ull; acc[i][1] = 0ull; }

    for (int k0 = 0; k0 < 64; k0 += 16) {
#pragma unroll
        for (int it = 0; it < 2; it++) {
            int e = tid + it * 256;
            int kk = e & 15, m = e >> 4;
            Hs[kk][m] = h[m * 512 + kb + k0 + kk];
        }
#pragma unroll
        for (int it = 0; it < 2; it++) {
            int s = tid + it * 256;
            int cq = s & 31, kr = s >> 5;
            *reinterpret_cast<float4*>(&Ws[kr][cq << 2]) =
                *reinterpret_cast<const float4*>(grk + (size_t)(kb + k0 + kr) * 1536 + n0 + (cq << 2));
        }
        __syncthreads();
#pragma unroll
        for (int kk = 0; kk < 16; kk++) {
            ulonglong2 bp = *reinterpret_cast<const ulonglong2*>(&Ws[kk][nx << 2]);
#pragma unroll
            for (int i = 0; i < 4; i++) {
                ull ad = pack2(Hs[kk][(my << 2) + i]);
                fma2(acc[i][0], ad, bp.x);
                fma2(acc[i][1], ad, bp.y);
            }
        }
        __syncthreads();
    }
    float* outp = g_mhp[blockIdx.y];
#pragma unroll
    for (int i = 0; i < 4; i++) {
        float2 v0 = unpack2(acc[i][0]);
        float2 v1 = unpack2(acc[i][1]);
        *reinterpret_cast<float4*>(&outp[((my << 2) + i) * 1536 + n0 + (nx << 2)]) =
            make_float4(v0.x, v0.y, v1.x, v1.y);
    }
}

// ---------------- Recurrence kernel B: sum 8 partials + GRU gates (mx precomputed) ----------------
__global__ void __launch_bounds__(512) gru_gates_kernel(const float* __restrict__ gb, int u) {
    const int b = blockIdx.x;
    const int j = threadIdx.x;
    float hz = 0.f, hr = 0.f, hh = 0.f;
#pragma unroll
    for (int c = 0; c < 8; c++) {
        const float* p = g_mhp[c] + b * 1536;
        hz += p[j];
        hr += p[512 + j];
        hh += p[1024 + j];
    }
    const float* br = gb + 1536;
    const float* mx = g_mx + ((size_t)u * 32 + b) * 1536;
    float xz = mx[j];
    float xr = mx[512 + j];
    float xh = mx[1024 + j];
    hz += br[j];
    hr += br[512 + j];
    hh += br[1024 + j];
    float z = 1.f / (1.f + expf(-(xz + hz)));
    float r = 1.f / (1.f + expf(-(xr + hr)));
    float cand = tanhf(xh + r * hh);
    float hold = g_hstate[u & 1][b * 512 + j];
    float hn = z * hold + (1.f - z) * cand;
    g_hstate[(u + 1) & 1][b * 512 + j] = hn;
    g_cat16[((size_t)u * 32 + b) * 1024 + j] = __float2half_rn(hn);
}

// ---------------- Batched softmax over 800 -> alpha16 (padded) ----------------
__global__ void __launch_bounds__(256) sm800_kernel() {
    const int row = blockIdx.x;
    const int tid = threadIdx.x;
    const float* sp = g_scoresall + (size_t)row * T1;
    __half* ap = g_alpha16 + (size_t)row * TPAD;
    __shared__ float sa[800];
    __shared__ float red[8], red2[8];
    const int w = tid >> 5, lane = tid & 31;

    float m = -1e30f;
    for (int t = tid; t < 800; t += 256) {
        float v = sp[t];
        sa[t] = v;
        m = fmaxf(m, v);
    }
#pragma unroll
    for (int o = 16; o; o >>= 1) m = fmaxf(m, __shfl_xor_sync(0xffffffffu, m, o));
    if (lane == 0) red[w] = m;
    __syncthreads();
    float mm = red[0];
#pragma unroll
    for (int i = 1; i < 8; i++) mm = fmaxf(mm, red[i]);

    float ps = 0.f;
    for (int t = tid; t < 800; t += 256) {
        float e = expf(sa[t] - mm);
        sa[t] = e;
        ps += e;
    }
#pragma unroll
    for (int o = 16; o; o >>= 1) ps += __shfl_xor_sync(0xffffffffu, ps, o);
    if (lane == 0) red2[w] = ps;
    __syncthreads();
    float sum = 0.f;
#pragma unroll
    for (int i = 0; i < 8; i++) sum += red2[i];
    const float inv = 1.f / sum;

    for (int t = tid; t < 800; t += 256) ap[t] = __float2half_rn(sa[t] * inv);
    if (tid < 32) ap[800 + tid] = __float2half(0.f);
}

// ---------------- Batched output softmax ----------------
__global__ void __launch_bounds__(256) outsm_all_kernel(float* __restrict__ out) {
    const int m = blockIdx.x;
    const int u = m >> 5, b = m & 31;
    const int tid = threadIdx.x;
    __shared__ float sh[1000];
    __shared__ float red[8], red2[8];
    const int w = tid >> 5, lane = tid & 31;
    const float* lp = g_logitsall + (size_t)m * 1000;

    float mx = -1e30f;
    for (int c = tid; c < 1000; c += 256) {
        float v = lp[c];
        sh[c] = v;
        mx = fmaxf(mx, v);
    }
#pragma unroll
    for (int o = 16; o; o >>= 1) mx = fmaxf(mx, __shfl_xor_sync(0xffffffffu, mx, o));
    if (lane == 0) red[w] = mx;
    __syncthreads();
    float mm = red[0];
#pragma unroll
    for (int i = 1; i < 8; i++) mm = fmaxf(mm, red[i]);

    float ps = 0.f;
    for (int c = tid; c < 1000; c += 256) {
        float e = expf(sh[c] - mm);
        sh[c] = e;
        ps += e;
    }
#pragma unroll
    for (int o = 16; o; o >>= 1) ps += __shfl_xor_sync(0xffffffffu, ps, o);
    if (lane == 0) red2[w] = ps;
    __syncthreads();
    float sum = 0.f;
#pragma unroll
    for (int i = 0; i < 8; i++) sum += red2[i];
    const float inv = 1.f / sum;

    float* op = out + ((size_t)b * USTEPS + u) * VOCABN;
    for (int c = tid; c < 1000; c += 256) op[c] = sh[c] * inv;
}

// ---------------- launch ----------------
extern "C" void kernel_launch(void* const* d_in, const int* in_sizes, int n_in,
                              void* d_out, int out_size) {
    const float* x        = (const float*)d_in[0];
    const int*   y        = (const int*)  d_in[1];
    const float* bn_gamma = (const float*)d_in[2];
    const float* bn_beta  = (const float*)d_in[3];
    const float* conv0_w  = (const float*)d_in[4];
    const float* conv0_b  = (const float*)d_in[5];
    const float* tcr_w    = (const float*)d_in[6];
    const float* tcr_b    = (const float*)d_in[7];
    const float* gru_k    = (const float*)d_in[8];
    const float* gru_rk   = (const float*)d_in[9];
    const float* gru_b    = (const float*)d_in[10];
    const float* fc_w     = (const float*)d_in[11];
    const float* fc_b     = (const float*)d_in[12];
    float* out = (float*)d_out;

    __half *a0, *a1, *wh, *x16, *wc16;
    cudaGetSymbolAddress((void**)&a0, g_sa0);
    cudaGetSymbolAddress((void**)&a1, g_sa1);
    cudaGetSymbolAddress((void**)&wh, g_wh);
    cudaGetSymbolAddress((void**)&x16, g_x16);
    cudaGetSymbolAddress((void**)&wc16, g_wc16);

    auto conv0k = conv16_kernel<T0, 2, 1, 128, 10, false>;
    auto tcrk   = conv16_kernel<T1, 1, 2, 512, 40, true>;
    cudaFuncSetAttribute(conv0k, cudaFuncAttributeMaxDynamicSharedMemorySize, CDSMEM);
    cudaFuncSetAttribute(tcrk,   cudaFuncAttributeMaxDynamicSharedMemorySize, CDSMEM);

    // side stream + fork/join events (host-side objects; no device allocation)
    cudaStream_t side;
    cudaStreamCreateWithFlags(&side, cudaStreamNonBlocking);
    cudaEvent_t ev_fork, ev_join;
    cudaEventCreateWithFlags(&ev_fork, cudaEventDisableTiming);
    cudaEventCreateWithFlags(&ev_join, cudaEventDisableTiming);

    // ---- shared prep (main stream) ----
    bn_stats_kernel<<<80, 256>>>(x, bn_gamma, bn_beta);
    zero_h_kernel<<<32, 512>>>();
    mx_kernel<<<dim3(USTEPS, B_), 256>>>(y, gru_k, gru_b);

    // ---- fork: decoder recurrence on side stream (independent of encoder) ----
    cudaEventRecord(ev_fork, 0);
    cudaStreamWaitEvent(side, ev_fork, 0);
    dim3 pgrid(12, 8);
    for (int u = 0; u < USTEPS; u++) {
        gru_part_kernel<<<pgrid, 256, 0, side>>>(gru_rk, u);
        gru_gates_kernel<<<32, 512, 0, side>>>(gru_b, u);
    }
    cudaEventRecord(ev_join, side);

    // ---- encoder on main stream ----
    dim3 wgrid(80, 16, 4);
    wsplit_kernel<<<wgrid, dim3(32, 8)>>>(tcr_w);
    fcwt_kernel<<<dim3(32, 32), dim3(32, 8)>>>(fc_w);
    wc0_kernel<<<(512 * 640 + 255) / 256, 256>>>(conv0_w);
    x16prep_kernel<<<(B_ * T0 * 128 + 255) / 256, 256>>>(x);

    dim3 cgrid(4, 200);
    conv0k<<<cgrid, 256, CDSMEM>>>(x16, wc16, conv0_b, a0);

    const size_t WT = (size_t)512 * 2560;
    tcrk<<<cgrid, 256, CDSMEM>>>(a0, wh + 0 * WT, tcr_b + 0 * 512, a1);
    tcrk<<<cgrid, 256, CDSMEM>>>(a1, wh + 1 * WT, tcr_b + 1 * 512, a0);
    tcrk<<<cgrid, 256, CDSMEM>>>(a0, wh + 2 * WT, tcr_b + 2 * 512, a1);
    tcrk<<<cgrid, 256, CDSMEM>>>(a1, wh + 3 * WT, tcr_b + 3 * 512, a0);
    // enc16 lives in g_sa0

    enct_kernel<<<dim3(26, 16, 32), dim3(32, 8)>>>();

    // ---- join: tail needs both enc (main) and cat16[:512] (side) ----
    cudaStreamWaitEvent(0, ev_join, 0);

    // ---- batched tail (all fp16 mma) ----
    scores16_kernel<<<dim3(7, 2, 32), 256>>>();
    sm800_kernel<<<USTEPS * B_, 256>>>();
    ctx16_kernel<<<dim3(4, 2, 32), 256>>>();
    fc16_kernel<<<dim3(8, 50), 256>>>(fc_b);
    outsm_all_kernel<<<USTEPS * B_, 256>>>(out);
}